// round 11
// baseline (speedup 1.0000x reference)
#include <cuda_runtime.h>

// B=1, C=32, H=128, W=256. Two warps per row (half 0: j<128, half 1: j>=128),
// 4 elems/lane. Warp scan gives within-half global inclusive prefixes in
// registers. For the dataset's dmin=0, dmax=64, window distance = 64 elems
// = 16 lanes, so lo = E[w-63] is shfl_up(16) of own registers; only half-1
// lanes 0-15 need half-0 values -> 64-entry smem patch + 64-thread named
// barrier. Half-0 lanes 0-15 are partial windows with lo = 0 (no lookup).
// Generic (dmin,dmax) fallback: per-row smem prefix table.

#define C_CH   32
#define H_DIM  128
#define W_DIM  256
#define FULLM  0xFFFFFFFFu
#define RPB    4               // rows per block (8 warps)

__global__ __launch_bounds__(256) void gcnet_hybrid_kernel(
        const float* __restrict__ feaR,
        const int* __restrict__ p_min,
        const int* __restrict__ p_max,
        float* __restrict__ out) {
    const int lane = threadIdx.x & 31;
    const int wrp  = threadIdx.x >> 5;        // 0..7
    const int rib  = wrp >> 1;                // row in block 0..3
    const int half = wrp & 1;
    const int row  = blockIdx.x * RPB + rib;  // 0..4095
    const int cr   = row >> 7;
    const int h    = row & 127;

    const int dmin = p_min[0] / 2;
    const int dmax = p_max[0] / 2;
    const int D    = dmax - dmin;
    const float mean_d  = 0.5f * (float)(dmin + dmax - 1);
    const float S_total = mean_d * (float)D;

    __shared__ float2 sE[RPB][272];           // fast: patch[0..64]; generic: E[0..256]
    __shared__ float2 sTot[RPB];
    float2* patch = sE[rib];

    const int j0 = half * 128 + 4 * lane;

    // ---- load 4 elems, exp, lane-local inclusive prefixes ----
    const float4 a = *(const float4*)(feaR + row * W_DIM + j0);
    const float p0 = __expf(a.x), p1 = __expf(a.y),
                p2 = __expf(a.z), p3 = __expf(a.w);
    const float jf = (float)j0;
    float s[4], sq[4];
    s[0] = p0;          sq[0] = jf * p0;
    s[1] = s[0] + p1;   sq[1] = fmaf(jf + 1.0f, p1, sq[0]);
    s[2] = s[1] + p2;   sq[2] = fmaf(jf + 2.0f, p2, sq[1]);
    s[3] = s[2] + p3;   sq[3] = fmaf(jf + 3.0f, p3, sq[2]);
    const float tp = s[3], tq = sq[3];

    // ---- warp inclusive scan of lane totals ----
    float ip = tp, iq = tq;
    #pragma unroll
    for (int off = 1; off < 32; off <<= 1) {
        const float xp = __shfl_up_sync(FULLM, ip, off);
        const float xq = __shfl_up_sync(FULLM, iq, off);
        if (lane >= off) { ip += xp; iq += xq; }
    }
    const float basep = ip - tp, baseq = iq - tq;   // within-half exclusive
    #pragma unroll
    for (int k = 0; k < 4; ++k) { s[k] += basep; sq[k] += baseq; }
    // s[k] = within-half-global inclusive prefix at j0+k (= E[j0+k+1] for half 0)

    // ---- left channel: constant fill ----
    {
        const float4 cst = make_float4(mean_d, mean_d, mean_d, mean_d);
        *(float4*)(out + (cr * H_DIM + h) * W_DIM + j0) = cst;
    }

    float* outR = out + ((cr + C_CH) * H_DIM + h) * W_DIM;
    float res[4];

    if (dmin == 0 && dmax == 64) {
        // ---- fast path ----
        if (half == 0) {
            if (lane >= 16) {               // publish E[65..128]
                const int b = 4 * (lane - 16);
                patch[b + 0] = make_float2(s[0], sq[0]);
                patch[b + 1] = make_float2(s[1], sq[1]);
                patch[b + 2] = make_float2(s[2], sq[2]);
                patch[b + 3] = make_float2(s[3], sq[3]);
            }
            if (lane == 31) patch[64] = make_float2(ip, iq);   // half-0 total
        }
        // 64-thread barrier between the two warps of this row.
        asm volatile("bar.sync %0, 64;" :: "r"(rib + 1) : "memory");

        float totP = 0.0f, totQ = 0.0f;
        if (half == 1) { const float2 t = patch[64]; totP = t.x; totQ = t.y; }

        #pragma unroll
        for (int k = 0; k < 4; ++k) {
            const float loSp = __shfl_up_sync(FULLM, s[k], 16);
            const float loSq = __shfl_up_sync(FULLM, sq[k], 16);
            const int   w  = j0 + k;
            const float wf = (float)w;
            if (half == 0 && lane < 16) {
                // partial window: d in [0, w], lo = 0
                const float denv = s[k], qd = sq[k];
                const float nv = wf + 1.0f;
                const float Sv = 0.5f * wf * nv;
                const float num = fmaf(wf, denv, S_total - Sv) - qd;
                const float den = denv + (64.0f - nv);
                res[k] = __fdividef(num, den);
            } else {
                float hiP = s[k], hiQ = sq[k], loP = loSp, loQ = loSq;
                if (half == 1 && lane < 16) {
                    const float2 t = patch[4 * lane + k];
                    loP = t.x; loQ = t.y;
                    hiP += totP; hiQ += totQ;
                }
                res[k] = wf - __fdividef(hiQ - loQ, hiP - loP);
            }
        }
    } else {
        // ---- generic fallback: per-row smem prefix table ----
        if (half == 0 && lane == 31) sTot[rib] = make_float2(ip, iq);
        __syncthreads();
        const float ap = half ? sTot[rib].x : 0.0f;
        const float aq = half ? sTot[rib].y : 0.0f;
        float2* E = sE[rib];
        #pragma unroll
        for (int k = 0; k < 4; ++k)
            E[j0 + k + 1] = make_float2(s[k] + ap, sq[k] + aq);
        if (half == 0 && lane == 0) E[0] = make_float2(0.0f, 0.0f);
        __syncthreads();
        #pragma unroll
        for (int k = 0; k < 4; ++k) {
            const int w = j0 + k;
            const int dhi = (dmax - 1) < w ? (dmax - 1) : w;
            int nv = dhi - dmin + 1; if (nv < 0) nv = 0;
            float denv = 0.0f, qd = 0.0f, Sv = 0.0f;
            if (nv > 0) {
                const float2 lo = E[w - dhi];
                const float2 hi = E[w - dmin + 1];
                denv = hi.x - lo.x; qd = hi.y - lo.y;
                Sv = 0.5f * (float)(dmin + dhi) * (float)nv;
            }
            const float num = fmaf((float)w, denv, S_total - Sv) - qd;
            const float den = denv + (float)(D - nv);
            res[k] = __fdividef(num, den);
        }
    }

    *(float4*)(outR + j0) = make_float4(res[0], res[1], res[2], res[3]);
}

extern "C" void kernel_launch(void* const* d_in, const int* in_sizes, int n_in,
                              void* d_out, int out_size) {
    // metadata order: feaL (unused), feaR, min_disp, max_disp
    const float* feaR = (const float*)d_in[1];
    const int* p_min  = (const int*)d_in[2];
    const int* p_max  = (const int*)d_in[3];
    float* out = (float*)d_out;

    const int rows = C_CH * H_DIM;            // 4096
    gcnet_hybrid_kernel<<<rows / RPB, 256>>>(feaR, p_min, p_max, out);
}

// round 12
// speedup vs baseline: 1.1422x; 1.1422x over previous
#include <cuda_runtime.h>

// B=1, C=32, H=128, W=256. Two warps per row (half 0: j<128, half 1: j>=128),
// 4 elems/lane. Warp scan gives within-half global inclusive prefixes in
// registers. For the dataset's dmin=0, dmax=64: window distance = 64 elems
// = 16 lanes, so lo = E[w-63] is shfl_up(16) of own registers; half-1 lanes
// 0-15 take lo from a 64-entry smem patch published by half-0 lanes 16-31
// (pre-offset by the half-0 total so hi stays raw). ONE __syncthreads()
// per block (named barriers in R11 capped occupancy at 3 CTAs/SM).
// Unified epilogue formula: full-window correction terms vanish naturally.
// Generic (dmin,dmax) fallback: per-row smem prefix table.

#define C_CH   32
#define H_DIM  128
#define W_DIM  256
#define FULLM  0xFFFFFFFFu
#define RPB    4               // rows per block (8 warps)

__global__ __launch_bounds__(256) void gcnet_v12_kernel(
        const float* __restrict__ feaR,
        const int* __restrict__ p_min,
        const int* __restrict__ p_max,
        float* __restrict__ out) {
    const int lane = threadIdx.x & 31;
    const int wrp  = threadIdx.x >> 5;        // 0..7
    const int rib  = wrp >> 1;                // row in block 0..3
    const int half = wrp & 1;
    const int row  = blockIdx.x * RPB + rib;  // 0..4095
    const int cr   = row >> 7;
    const int h    = row & 127;

    const int dmin = p_min[0] / 2;
    const int dmax = p_max[0] / 2;
    const int D    = dmax - dmin;
    const float mean_d  = 0.5f * (float)(dmin + dmax - 1);
    const float S_total = mean_d * (float)D;

    __shared__ float2 sE[RPB][260];           // fast: patch[0..64]; generic: E[0..256]
    __shared__ float2 sTot[RPB];
    float2* patch = sE[rib];

    const int j0 = half * 128 + 4 * lane;

    // ---- load 4 elems, exp, lane-local inclusive prefixes ----
    const float4 a = *(const float4*)(feaR + row * W_DIM + j0);
    const float p0 = __expf(a.x), p1 = __expf(a.y),
                p2 = __expf(a.z), p3 = __expf(a.w);
    const float jf = (float)j0;
    float s[4], sq[4];
    s[0] = p0;          sq[0] = jf * p0;
    s[1] = s[0] + p1;   sq[1] = fmaf(jf + 1.0f, p1, sq[0]);
    s[2] = s[1] + p2;   sq[2] = fmaf(jf + 2.0f, p2, sq[1]);
    s[3] = s[2] + p3;   sq[3] = fmaf(jf + 3.0f, p3, sq[2]);
    const float tp = s[3], tq = sq[3];

    // ---- warp inclusive scan of lane totals ----
    float ip = tp, iq = tq;
    #pragma unroll
    for (int off = 1; off < 32; off <<= 1) {
        const float xp = __shfl_up_sync(FULLM, ip, off);
        const float xq = __shfl_up_sync(FULLM, iq, off);
        if (lane >= off) { ip += xp; iq += xq; }
    }
    const float basep = ip - tp, baseq = iq - tq;   // within-half exclusive
    #pragma unroll
    for (int k = 0; k < 4; ++k) { s[k] += basep; sq[k] += baseq; }
    // s[k] = within-half inclusive prefix at j0+k (= E[j0+k+1] for half 0)

    // ---- left channel: constant fill ----
    {
        const float4 cst = make_float4(mean_d, mean_d, mean_d, mean_d);
        *(float4*)(out + (cr * H_DIM + h) * W_DIM + j0) = cst;
    }

    float* outR = out + ((cr + C_CH) * H_DIM + h) * W_DIM;
    float res[4];

    if (dmin == 0 && dmax == 64) {
        // ---- fast path ----
        if (half == 0) {
            if (lane >= 16) {               // publish E[65..128]
                const int b = 4 * (lane - 16);
                patch[b + 0] = make_float2(s[0], sq[0]);
                patch[b + 1] = make_float2(s[1], sq[1]);
                patch[b + 2] = make_float2(s[2], sq[2]);
                patch[b + 3] = make_float2(s[3], sq[3]);
            }
            if (lane == 31) patch[64] = make_float2(ip, iq);   // half-0 total
        }
        __syncthreads();

        float totP = 0.0f, totQ = 0.0f;
        if (half == 1) { const float2 t = patch[64]; totP = t.x; totQ = t.y; }
        const bool fromPatch = (half == 1) && (lane < 16);
        const bool fromShfl  = (lane >= 16);

        #pragma unroll
        for (int k = 0; k < 4; ++k) {
            const float loSp = __shfl_up_sync(FULLM, s[k], 16);
            const float loSq = __shfl_up_sync(FULLM, sq[k], 16);
            const int   w  = j0 + k;
            const float wf = (float)w;

            float loP, loQ;
            if (fromPatch) {
                const float2 t = patch[4 * lane + k];
                loP = t.x - totP;           // pre-offset: hi stays raw
                loQ = t.y - totQ;
            } else {
                loP = fromShfl ? loSp : 0.0f;
                loQ = fromShfl ? loSq : 0.0f;
            }
            const float denv = s[k] - loP;
            const float qd   = sq[k] - loQ;
            // unified formula: correction terms vanish for full windows
            const int   dhi = (w < 63) ? w : 63;
            const float nv  = (float)(dhi + 1);
            const float Sv  = 0.5f * (float)dhi * nv;
            const float num = fmaf(wf, denv, S_total - Sv) - qd;
            const float den = denv + (64.0f - nv);
            res[k] = __fdividef(num, den);
        }
    } else {
        // ---- generic fallback: per-row smem prefix table ----
        if (half == 0 && lane == 31) sTot[rib] = make_float2(ip, iq);
        __syncthreads();
        const float ap = half ? sTot[rib].x : 0.0f;
        const float aq = half ? sTot[rib].y : 0.0f;
        float2* E = sE[rib];
        #pragma unroll
        for (int k = 0; k < 4; ++k)
            E[j0 + k + 1] = make_float2(s[k] + ap, sq[k] + aq);
        if (half == 0 && lane == 0) E[0] = make_float2(0.0f, 0.0f);
        __syncthreads();
        #pragma unroll
        for (int k = 0; k < 4; ++k) {
            const int w = j0 + k;
            const int dhi = (dmax - 1) < w ? (dmax - 1) : w;
            int nv = dhi - dmin + 1; if (nv < 0) nv = 0;
            float denv = 0.0f, qd = 0.0f, Sv = 0.0f;
            if (nv > 0) {
                const float2 lo = E[w - dhi];
                const float2 hi = E[w - dmin + 1];
                denv = hi.x - lo.x; qd = hi.y - lo.y;
                Sv = 0.5f * (float)(dmin + dhi) * (float)nv;
            }
            const float num = fmaf((float)w, denv, S_total - Sv) - qd;
            const float den = denv + (float)(D - nv);
            res[k] = __fdividef(num, den);
        }
    }

    *(float4*)(outR + j0) = make_float4(res[0], res[1], res[2], res[3]);
}

extern "C" void kernel_launch(void* const* d_in, const int* in_sizes, int n_in,
                              void* d_out, int out_size) {
    // metadata order: feaL (unused), feaR, min_disp, max_disp
    const float* feaR = (const float*)d_in[1];
    const int* p_min  = (const int*)d_in[2];
    const int* p_max  = (const int*)d_in[3];
    float* out = (float*)d_out;

    const int rows = C_CH * H_DIM;            // 4096
    gcnet_v12_kernel<<<rows / RPB, 256>>>(feaR, p_min, p_max, out);
}